// round 15
// baseline (speedup 1.0000x reference)
#include <cuda_runtime.h>
#include <cuda_bf16.h>
#include <cstdint>

// Problem constants
#define NTOK  32768
#define KDIM  256
#define NE    1024
#define HW    1024

// Output layout (flattened tuple, float32). OFF_D*4 % 16 == 4; but
// (OFF_D + row*1024 + col) is 16B-aligned for col == 3 (mod 4).
#define OFF_ZQ   0
#define OFF_LOSS 8388608
#define OFF_IDX  8388609
#define OFF_D    8421377ll

#define REFINE_TH 2e-3f

// ---------------------------------------------------------------------------
// Scratch (static device arrays; no allocations allowed)
__device__ float  g_znorm[NTOK];
__device__ float  g_enorm[NE];
__device__ float  g_pval[8][NTOK];   // per n-tile best value
__device__ float  g_psec[8][NTOK];   // per n-tile second-best value
__device__ int    g_pidx[8][NTOK];   // per n-tile best index
__device__ double g_lpart[1024];
__device__ __align__(1024) __nv_bfloat16 g_Ahi[NTOK * KDIM];  // tokens, K-major, bf16
__device__ __align__(1024) __nv_bfloat16 g_Bhi[NE * KDIM];    // codes,  K-major, bf16

// ---------------------------------------------------------------------------
__device__ __forceinline__ uint32_t smem_u32(const void* p) {
    uint32_t a;
    asm("{ .reg .u64 t; cvta.to.shared.u64 t, %1; cvt.u32.u64 %0, t; }" : "=r"(a) : "l"(p));
    return a;
}
__device__ __forceinline__ void cp16(uint32_t dst, const void* src) {
    asm volatile("cp.async.cg.shared.global [%0], [%1], 16;" :: "r"(dst), "l"(src));
}
__device__ __forceinline__ void cp_commit() {
    asm volatile("cp.async.commit_group;" ::: "memory");
}
template <int N> __device__ __forceinline__ void cp_wait() {
    asm volatile("cp.async.wait_group %0;" :: "n"(N) : "memory");
}
__device__ __forceinline__ void ldsm4(uint32_t& r0, uint32_t& r1, uint32_t& r2, uint32_t& r3,
                                      uint32_t addr) {
    asm volatile("ldmatrix.sync.aligned.m8n8.x4.shared.b16 {%0,%1,%2,%3}, [%4];"
                 : "=r"(r0), "=r"(r1), "=r"(r2), "=r"(r3) : "r"(addr));
}
__device__ __forceinline__ void mma16816(float* c, const uint32_t* a, const uint32_t* b) {
    asm volatile(
        "mma.sync.aligned.m16n8k16.row.col.f32.bf16.bf16.f32 "
        "{%0,%1,%2,%3}, {%4,%5,%6,%7}, {%8,%9}, {%0,%1,%2,%3};"
        : "+f"(c[0]), "+f"(c[1]), "+f"(c[2]), "+f"(c[3])
        : "r"(a[0]), "r"(a[1]), "r"(a[2]), "r"(a[3]), "r"(b[0]), "r"(b[1]));
}
// Merge (b1,i1,b2) <- other (ob1,oi1,ob2); strict compare + index tie-break.
#define MERGE3(b1, i1, b2, ob1, oi1, ob2) do {                     \
    if ((ob1) < (b1) || ((ob1) == (b1) && (oi1) < (i1))) {         \
        (b2) = fminf((b1), (ob2)); (b1) = (ob1); (i1) = (oi1);     \
    } else {                                                       \
        (b2) = fminf((b2), (ob1));                                 \
    }                                                              \
} while (0)

// ---------------------------------------------------------------------------
// prep_e2: e -> bf16 K-major + enorm, fused. One block (128 thr) per code row.
__global__ __launch_bounds__(128) void prep_e2(const float* __restrict__ e) {
    __shared__ float wsum[4];
    int row = blockIdx.x;
    int tid = threadIdx.x;
    int lane = tid & 31, warp = tid >> 5;
    float2 v = ((const float2*)e)[row * 128 + tid];
    __nv_bfloat162 hp;
    hp.x = __float2bfloat16(v.x);
    hp.y = __float2bfloat16(v.y);
    ((uint32_t*)g_Bhi)[row * 128 + tid] = *(uint32_t*)&hp;
    float s = fmaf(v.x, v.x, v.y * v.y);
#pragma unroll
    for (int o = 16; o; o >>= 1) s += __shfl_xor_sync(0xFFFFFFFFu, s, o);
    if (lane == 0) wsum[warp] = s;
    __syncthreads();
    if (tid == 0) g_enorm[row] = wsum[0] + wsum[1] + wsum[2] + wsum[3];
}

// prep_z: NCHW -> token-major bf16 (g_Ahi) + znorm. 32 tokens/block.
__global__ __launch_bounds__(256) void prep_z(const float* __restrict__ z) {
    __shared__ float ts[KDIM][33];
    __shared__ float zp[8][32];
    int tid = threadIdx.x;
    int tb  = blockIdx.x;
    int b   = tb >> 5;
    int hw0 = (tb * 32) & 1023;
    const float* zb = z + (size_t)b * KDIM * HW + hw0;
    int lane32 = tid & 31, cb = tid >> 5;
#pragma unroll
    for (int i = 0; i < 32; i++) {
        int c = i * 8 + cb;
        ts[c][lane32] = zb[(size_t)c * HW + lane32];
    }
    __syncthreads();
    // znorm partials
    float s = 0.f;
#pragma unroll
    for (int i = 0; i < 32; i++) {
        float v = ts[cb * 32 + i][lane32];
        s = fmaf(v, v, s);
    }
    zp[cb][lane32] = s;
    __syncthreads();
    if (tid < 32) {
        float t = 0.f;
#pragma unroll
        for (int u = 0; u < 8; u++) t += zp[u][tid];
        g_znorm[tb * 32 + tid] = t;
    }
    // write bf16 token rows
    int t = tid >> 3, part = tid & 7;
    uint32_t* ah = (uint32_t*)g_Ahi + (size_t)(tb * 32 + t) * 128 + part * 16;
#pragma unroll
    for (int i = 0; i < 16; i++) {
        __nv_bfloat162 hp;
        hp.x = __float2bfloat16(ts[part * 32 + 2 * i][t]);
        hp.y = __float2bfloat16(ts[part * 32 + 2 * i + 1][t]);
        ah[i] = *(uint32_t*)&hp;
    }
}

// ---------------------------------------------------------------------------
// Persistent GEMM: grid (8 n-tiles, 37 m-slots). B n-tile resident in SMEM;
// A streamed via 2-stage cp.async. Epilogue stages each 16x128 d block through
// a small smem buffer so global stores are STG.128 (aligned at col==3 mod 4).
#define MSLOTS   37
#define SM_B     0            // 4 chunks x 16384 = 65536
#define SM_A     65536        // 2 stages x 16384 = 32768
#define SM_EN    98304        // 512
#define SM_RED   98816        // sv1 2048 | sv2 2048 | six 2048
#define SM_BUF   104960       // 16 rows x 132 floats = 8448
#define SM_GTOT  113408

__global__ __launch_bounds__(256, 2) void gemm_mma(float* __restrict__ out) {
    extern __shared__ char smem[];
    uint32_t sb = smem_u32(smem);
    int tid  = threadIdx.x;
    int lane = tid & 31, warp = tid >> 5;
    int wy = warp & 1, wx = warp >> 1;          // 2 (M) x 4 (N) warps
    int nidx  = blockIdx.x;
    int mslot = blockIdx.y;
    int j0 = nidx * 128;
    int T  = (mslot < 34) ? 7 : 6;              // 256 = 34*7 + 3*6
    int G  = T * 4;

    float* s_en = (float*)(smem + SM_EN);
    if (tid < 128) s_en[tid] = g_enorm[j0 + tid];

    // ---- Load full B n-tile (4 chunks of 16KB), one cp.async group
    {
#pragma unroll
        for (int kc = 0; kc < 4; kc++)
#pragma unroll
            for (int i = 0; i < 4; i++) {
                int ch = tid + i * 256;           // 0..1023
                int r = ch >> 3, cc = ch & 7;
                uint32_t sw = (uint32_t)(r * 128 + ((cc ^ (r & 7)) << 4));
                cp16(sb + SM_B + kc * 16384 + sw,
                     (const char*)g_Bhi + ((size_t)(j0 + r) * KDIM + kc * 64 + cc * 8) * 2);
            }
        cp_commit();
    }

    // A chunk loader: tile tl, chunk c -> stage s
    auto load_A = [&](int tl, int c, int s) {
        int m0 = (mslot + tl * MSLOTS) * 128;
        uint32_t base = sb + SM_A + s * 16384;
#pragma unroll
        for (int i = 0; i < 4; i++) {
            int ch = tid + i * 256;
            int r = ch >> 3, cc = ch & 7;
            uint32_t sw = (uint32_t)(r * 128 + ((cc ^ (r & 7)) << 4));
            cp16(base + sw,
                 (const char*)g_Ahi + ((size_t)(m0 + r) * KDIM + c * 64 + cc * 8) * 2);
        }
        cp_commit();
    };

    load_A(0, 0, 0);
    load_A(0, 1, 1);

    float acc[4][4][4];
#pragma unroll
    for (int a = 0; a < 4; a++)
#pragma unroll
        for (int b = 0; b < 4; b++)
#pragma unroll
            for (int c = 0; c < 4; c++) acc[a][b][c] = 0.f;

    float* sv1  = (float*)(smem + SM_RED);
    float* sv2  = sv1 + 512;
    int*   six  = (int*)(sv2 + 512);
    float* sbuf = (float*)(smem + SM_BUF);

    for (int g = 0; g < G; g++) {
        int c = g & 3, s = g & 1, tl = g >> 2;
        int m0 = (mslot + tl * MSLOTS) * 128;
        if (g + 2 < G) cp_wait<1>(); else cp_wait<0>();
        __syncthreads();

        uint32_t sa  = sb + SM_A + s * 16384;
        uint32_t sbb = sb + SM_B + c * 16384;
#pragma unroll
        for (int k16 = 0; k16 < 4; k16++) {
            uint32_t af[4][4];
#pragma unroll
            for (int mf = 0; mf < 4; mf++) {
                int row = wy * 64 + mf * 16 + (lane & 15);
                int ch  = k16 * 2 + (lane >> 4);
                uint32_t addr = sa + row * 128 + (((ch ^ (row & 7))) << 4);
                ldsm4(af[mf][0], af[mf][1], af[mf][2], af[mf][3], addr);
            }
            uint32_t bf[4][2];
#pragma unroll
            for (int h = 0; h < 2; h++) {
                int row = wx * 32 + h * 16 + ((lane >> 4) << 3) + (lane & 7);
                int ch  = k16 * 2 + ((lane >> 3) & 1);
                uint32_t addr = sbb + row * 128 + (((ch ^ (row & 7))) << 4);
                uint32_t r0, r1, r2, r3;
                ldsm4(r0, r1, r2, r3, addr);
                bf[2 * h][0] = r0; bf[2 * h][1] = r1;
                bf[2 * h + 1][0] = r2; bf[2 * h + 1][1] = r3;
            }
#pragma unroll
            for (int mf = 0; mf < 4; mf++)
#pragma unroll
                for (int nf = 0; nf < 4; nf++)
                    mma16816(acc[mf][nf], af[mf], bf[nf]);
        }
        __syncthreads();
        if (g + 2 < G) load_A((g + 2) >> 2, (g + 2) & 3, s);

        if (c == 3) {
            // ---- Tile epilogue: per (mf,h) stage 16x128 d values in smem,
            // then store coalesced (STG.128 at col==3 mod 4 + 4 edge scalars).
#pragma unroll
            for (int mf = 0; mf < 4; mf++) {
#pragma unroll
                for (int h = 0; h < 2; h++) {
                    int r4   = lane >> 2;                    // 0..7
                    int row  = wy * 64 + mf * 16 + 8 * h + r4;
                    int brow = wy * 8 + r4;                  // buffer row 0..15
                    float zn = g_znorm[m0 + row];
                    float b1 = 3.4e38f, b2 = 3.4e38f;
                    int   i1 = 0;
                    float* srow = sbuf + brow * 132 + 1 + wx * 32;
#pragma unroll
                    for (int nf = 0; nf < 4; nf++) {
#pragma unroll
                        for (int q = 0; q < 2; q++) {
                            int lcol = nf * 8 + 2 * (lane & 3) + q;
                            int col  = wx * 32 + lcol;
                            float v = fmaf(-2.f, acc[mf][nf][2 * h + q], zn + s_en[col]);
                            srow[lcol] = v;
                            if (v < b1)      { b2 = b1; b1 = v; i1 = j0 + col; }
                            else if (v < b2) { b2 = v; }
                        }
                    }
#pragma unroll
                    for (int off = 1; off < 4; off <<= 1) {
                        float ob1 = __shfl_xor_sync(0xFFFFFFFFu, b1, off);
                        float ob2 = __shfl_xor_sync(0xFFFFFFFFu, b2, off);
                        int   oi1 = __shfl_xor_sync(0xFFFFFFFFu, i1, off);
                        MERGE3(b1, i1, b2, ob1, oi1, ob2);
                    }
                    if ((lane & 3) == 0) {
                        sv1[row * 4 + wx] = b1;
                        sv2[row * 4 + wx] = b2;
                        six[row * 4 + wx] = i1;
                    }
                    __syncthreads();
                    // coalesced writeback of the 16 staged rows
                    {
                        int row16 = tid >> 4;                // 0..15
                        int ii    = tid & 15;                // 0..15
                        int grow  = m0 + ((row16 < 8) ? (mf * 16 + 8 * h + row16)
                                                      : (64 + mf * 16 + 8 * h + row16 - 8));
                        float* drow = out + OFF_D + (size_t)grow * NE + j0;
                        const float* sr = sbuf + row16 * 132 + 1;
                        float4 va = *(const float4*)(sr + 3 + 4 * ii);
                        *(float4*)(drow + 3 + 4 * ii) = va;
                        if (ii < 15) {
                            float4 vb = *(const float4*)(sr + 67 + 4 * ii);
                            *(float4*)(drow + 67 + 4 * ii) = vb;
                        } else {
                            drow[0]   = sr[0];
                            drow[1]   = sr[1];
                            drow[2]   = sr[2];
                            drow[127] = sr[127];
                        }
                    }
                    __syncthreads();
                }
            }
            if (tid < 128) {
                float b1 = sv1[tid * 4], b2 = sv2[tid * 4];
                int   i1 = six[tid * 4];
#pragma unroll
                for (int u = 1; u < 4; u++) {
                    float ob1 = sv1[tid * 4 + u], ob2 = sv2[tid * 4 + u];
                    int   oi1 = six[tid * 4 + u];
                    MERGE3(b1, i1, b2, ob1, oi1, ob2);
                }
                g_pval[nidx][m0 + tid] = b1;
                g_psec[nidx][m0 + tid] = b2;
                g_pidx[nidx][m0 + tid] = i1;
            }
            // reset accumulators for next tile
#pragma unroll
            for (int a = 0; a < 4; a++)
#pragma unroll
                for (int b = 0; b < 4; b++)
#pragma unroll
                    for (int cc2 = 0; cc2 < 4; cc2++) acc[a][b][cc2] = 0.f;
        }
    }
}

// ---------------------------------------------------------------------------
// finalize: fused refine + z_q. 32 tokens/block.
// Phase 1: each warp resolves 4 tokens (triple merge + tile-targeted exact
// refine reading z directly from NCHW). Phase 2: gather e rows, write z_q,
// min_idx done in phase 1; deterministic loss partials.
__global__ __launch_bounds__(256) void finalize(const float* __restrict__ z,
                                                const float* __restrict__ e,
                                                float* __restrict__ out) {
    __shared__ int    s_idx[32];
    __shared__ float  s_e[KDIM][33];
    __shared__ double s_red[8];

    int tid  = threadIdx.x;
    int lane = tid & 31;
    int wid  = tid >> 5;
    int t0   = blockIdx.x * 32;

    // ---- Phase 1: merge + refine, 4 tokens per warp
#pragma unroll
    for (int k = 0; k < 4; k++) {
        int tl = wid + k * 8;
        int t  = t0 + tl;

        float tb1 = 3.4e38f, tb2 = 3.4e38f;
        int   tix = 0x7FFFFFFF;
        if (lane < 8) {
            tb1 = g_pval[lane][t];
            tb2 = g_psec[lane][t];
            tix = g_pidx[lane][t];
        }
        float b1 = tb1, b2 = tb2;
        int   i1 = tix;
#pragma unroll
        for (int off = 1; off < 8; off <<= 1) {
            float ob1 = __shfl_xor_sync(0xFFFFFFFFu, b1, off);
            float ob2 = __shfl_xor_sync(0xFFFFFFFFu, b2, off);
            int   oi1 = __shfl_xor_sync(0xFFFFFFFFu, i1, off);
            MERGE3(b1, i1, b2, ob1, oi1, ob2);
        }
        b1 = __shfl_sync(0xFFFFFFFFu, b1, 0);
        b2 = __shfl_sync(0xFFFFFFFFu, b2, 0);
        i1 = __shfl_sync(0xFFFFFFFFu, i1, 0);

        int besti = i1;
        if (b2 - b1 < REFINE_TH) {
            float thresh = b1 + REFINE_TH;
            int bq = t >> 10;
            int hw = t & 1023;
            const float* zb = z + (size_t)bq * KDIM * HW + hw;
            float zr[8];
#pragma unroll
            for (int u = 0; u < 8; u++) zr[u] = zb[(size_t)(lane + 32 * u) * HW];
            float zn    = g_znorm[t];
            float bestv = 3.4e38f;

            auto eval = [&](int j) {
                const float* erow = e + (size_t)j * KDIM;
                float d = 0.f;
#pragma unroll
                for (int u = 0; u < 8; u++) d = fmaf(zr[u], erow[lane + 32 * u], d);
#pragma unroll
                for (int o = 16; o; o >>= 1) d += __shfl_xor_sync(0xFFFFFFFFu, d, o);
                float ex = fmaf(-2.f, d, zn + g_enorm[j]);
                if (ex < bestv) { bestv = ex; besti = j; }   // ascending j: first-min wins
            };

            for (int u = 0; u < 8; u++) {
                float ub1 = __shfl_sync(0xFFFFFFFFu, tb1, u);
                if (ub1 >= thresh) continue;
                float ub2 = __shfl_sync(0xFFFFFFFFu, tb2, u);
                if (ub2 < thresh) {
                    const float* drow = out + OFF_D + (size_t)t * NE + u * 128;
                    float dv[4];
#pragma unroll
                    for (int kk = 0; kk < 4; kk++) dv[kk] = drow[lane + 32 * kk];
#pragma unroll
                    for (int kk = 0; kk < 4; kk++) {
                        unsigned msk = __ballot_sync(0xFFFFFFFFu, dv[kk] < thresh);
                        while (msk) {
                            int src = __ffs(msk) - 1;
                            msk &= msk - 1;
                            eval(u * 128 + src + 32 * kk);
                        }
                    }
                } else {
                    eval(__shfl_sync(0xFFFFFFFFu, tix, u));
                }
            }
        }
        if (lane == 0) {
            s_idx[tl] = besti;
            out[OFF_IDX + t] = (float)besti;
        }
    }
    __syncthreads();

    // ---- Phase 2: gather embedding rows (transposed), write z_q, loss partials
#pragma unroll
    for (int u = 0; u < 4; u++) {
        int tt = wid * 4 + u;
        const float* row = e + (size_t)s_idx[tt] * KDIM;
#pragma unroll
        for (int v = 0; v < 8; v++) {
            int c = lane + 32 * v;
            s_e[c][tt] = row[c];
        }
    }
    __syncthreads();

    int b   = t0 >> 10;
    int hw0 = t0 & 1023;
    const float* zb = z + (size_t)b * KDIM * HW + hw0;
    float*       qb = out + OFF_ZQ + (size_t)b * KDIM * HW + hw0;

    float ls = 0.f;
#pragma unroll 4
    for (int ci = 0; ci < 32; ci++) {
        int c = wid + ci * 8;
        float zv  = zb[(size_t)c * HW + lane];
        float ev  = s_e[c][lane];
        float dqz = ev - zv;
        qb[(size_t)c * HW + lane] = zv + dqz;
        ls = fmaf(dqz, dqz, ls);
    }
#pragma unroll
    for (int o = 16; o; o >>= 1) ls += __shfl_xor_sync(0xFFFFFFFFu, ls, o);
    if (lane == 0) s_red[wid] = (double)ls;
    __syncthreads();
    if (tid == 0) {
        double s = 0.0;
#pragma unroll
        for (int u = 0; u < 8; u++) s += s_red[u];
        g_lpart[blockIdx.x] = s;
    }
}

__global__ __launch_bounds__(256) void loss_kernel(float* __restrict__ out) {
    __shared__ double s_red[256];
    int tid = threadIdx.x;
    double s = 0.0;
#pragma unroll
    for (int u = 0; u < 4; u++) s += g_lpart[tid * 4 + u];
    s_red[tid] = s;
    __syncthreads();
    for (int o = 128; o; o >>= 1) {
        if (tid < o) s_red[tid] += s_red[tid + o];
        __syncthreads();
    }
    if (tid == 0) out[OFF_LOSS] = (float)(1.25 * s_red[0] / 8388608.0);
}

// ---------------------------------------------------------------------------
extern "C" void kernel_launch(void* const* d_in, const int* in_sizes, int n_in,
                              void* d_out, int out_size) {
    const float* z = (const float*)d_in[0];
    const float* e = (const float*)d_in[1];
    float* out = (float*)d_out;

    cudaFuncSetAttribute(gemm_mma, cudaFuncAttributeMaxDynamicSharedMemorySize, SM_GTOT);

    prep_e2<<<NE, 128>>>(e);
    prep_z<<<1024, 256>>>(z);
    {
        dim3 grid(8, MSLOTS);       // persistent: n-tile x m-slot
        gemm_mma<<<grid, 256, SM_GTOT>>>(out);
    }
    finalize<<<NTOK / 32, 256>>>(z, e, out);
    loss_kernel<<<1, 256>>>(out);
}

// round 16
// speedup vs baseline: 1.0626x; 1.0626x over previous
#include <cuda_runtime.h>
#include <cuda_bf16.h>
#include <cstdint>

// Problem constants
#define NTOK  32768
#define KDIM  256
#define NE    1024
#define HW    1024

// Output layout (flattened tuple, float32). OFF_D*4 % 16 == 4; but
// (OFF_D + row*1024 + col) is 16B-aligned for col == 3 (mod 4).
#define OFF_ZQ   0
#define OFF_LOSS 8388608
#define OFF_IDX  8388609
#define OFF_D    8421377ll

#define REFINE_TH 2e-3f

// ---------------------------------------------------------------------------
// Scratch (static device arrays; no allocations allowed)
__device__ float  g_znorm[NTOK];
__device__ float  g_enorm[NE];
__device__ float  g_pval[8][NTOK];   // per n-tile best value
__device__ float  g_psec[8][NTOK];   // per n-tile second-best value
__device__ int    g_pidx[8][NTOK];   // per n-tile best index
__device__ int    g_idx[NTOK];       // resolved final index
__device__ double g_lpart[1024];
__device__ __align__(1024) __nv_bfloat16 g_Ahi[NTOK * KDIM];  // tokens, K-major, bf16
__device__ __align__(1024) __nv_bfloat16 g_Bhi[NE * KDIM];    // codes,  K-major, bf16

// ---------------------------------------------------------------------------
__device__ __forceinline__ uint32_t smem_u32(const void* p) {
    uint32_t a;
    asm("{ .reg .u64 t; cvta.to.shared.u64 t, %1; cvt.u32.u64 %0, t; }" : "=r"(a) : "l"(p));
    return a;
}
__device__ __forceinline__ void cp16(uint32_t dst, const void* src) {
    asm volatile("cp.async.cg.shared.global [%0], [%1], 16;" :: "r"(dst), "l"(src));
}
__device__ __forceinline__ void cp_commit() {
    asm volatile("cp.async.commit_group;" ::: "memory");
}
template <int N> __device__ __forceinline__ void cp_wait() {
    asm volatile("cp.async.wait_group %0;" :: "n"(N) : "memory");
}
__device__ __forceinline__ void ldsm4(uint32_t& r0, uint32_t& r1, uint32_t& r2, uint32_t& r3,
                                      uint32_t addr) {
    asm volatile("ldmatrix.sync.aligned.m8n8.x4.shared.b16 {%0,%1,%2,%3}, [%4];"
                 : "=r"(r0), "=r"(r1), "=r"(r2), "=r"(r3) : "r"(addr));
}
__device__ __forceinline__ void mma16816(float* c, const uint32_t* a, const uint32_t* b) {
    asm volatile(
        "mma.sync.aligned.m16n8k16.row.col.f32.bf16.bf16.f32 "
        "{%0,%1,%2,%3}, {%4,%5,%6,%7}, {%8,%9}, {%0,%1,%2,%3};"
        : "+f"(c[0]), "+f"(c[1]), "+f"(c[2]), "+f"(c[3])
        : "r"(a[0]), "r"(a[1]), "r"(a[2]), "r"(a[3]), "r"(b[0]), "r"(b[1]));
}
// Merge (b1,i1,b2) <- other (ob1,oi1,ob2); strict compare + index tie-break.
#define MERGE3(b1, i1, b2, ob1, oi1, ob2) do {                     \
    if ((ob1) < (b1) || ((ob1) == (b1) && (oi1) < (i1))) {         \
        (b2) = fminf((b1), (ob2)); (b1) = (ob1); (i1) = (oi1);     \
    } else {                                                       \
        (b2) = fminf((b2), (ob1));                                 \
    }                                                              \
} while (0)

// ---------------------------------------------------------------------------
// prep_e2: e -> bf16 K-major + enorm, fused. One block (128 thr) per code row.
__global__ __launch_bounds__(128) void prep_e2(const float* __restrict__ e) {
    __shared__ float wsum[4];
    int row = blockIdx.x;
    int tid = threadIdx.x;
    int lane = tid & 31, warp = tid >> 5;
    float2 v = ((const float2*)e)[row * 128 + tid];
    __nv_bfloat162 hp;
    hp.x = __float2bfloat16(v.x);
    hp.y = __float2bfloat16(v.y);
    ((uint32_t*)g_Bhi)[row * 128 + tid] = *(uint32_t*)&hp;
    float s = fmaf(v.x, v.x, v.y * v.y);
#pragma unroll
    for (int o = 16; o; o >>= 1) s += __shfl_xor_sync(0xFFFFFFFFu, s, o);
    if (lane == 0) wsum[warp] = s;
    __syncthreads();
    if (tid == 0) g_enorm[row] = wsum[0] + wsum[1] + wsum[2] + wsum[3];
}

// prep_z: NCHW -> token-major bf16 (g_Ahi) + znorm. 32 tokens/block.
__global__ __launch_bounds__(256) void prep_z(const float* __restrict__ z) {
    __shared__ float ts[KDIM][33];
    __shared__ float zp[8][32];
    int tid = threadIdx.x;
    int tb  = blockIdx.x;
    int b   = tb >> 5;
    int hw0 = (tb * 32) & 1023;
    const float* zb = z + (size_t)b * KDIM * HW + hw0;
    int lane32 = tid & 31, cb = tid >> 5;
#pragma unroll
    for (int i = 0; i < 32; i++) {
        int c = i * 8 + cb;
        ts[c][lane32] = zb[(size_t)c * HW + lane32];
    }
    __syncthreads();
    // znorm partials
    float s = 0.f;
#pragma unroll
    for (int i = 0; i < 32; i++) {
        float v = ts[cb * 32 + i][lane32];
        s = fmaf(v, v, s);
    }
    zp[cb][lane32] = s;
    __syncthreads();
    if (tid < 32) {
        float t = 0.f;
#pragma unroll
        for (int u = 0; u < 8; u++) t += zp[u][tid];
        g_znorm[tb * 32 + tid] = t;
    }
    // write bf16 token rows
    int t = tid >> 3, part = tid & 7;
    uint32_t* ah = (uint32_t*)g_Ahi + (size_t)(tb * 32 + t) * 128 + part * 16;
#pragma unroll
    for (int i = 0; i < 16; i++) {
        __nv_bfloat162 hp;
        hp.x = __float2bfloat16(ts[part * 32 + 2 * i][t]);
        hp.y = __float2bfloat16(ts[part * 32 + 2 * i + 1][t]);
        ah[i] = *(uint32_t*)&hp;
    }
}

// ---------------------------------------------------------------------------
// Persistent GEMM: grid (8 n-tiles, 37 m-slots). B n-tile resident in SMEM;
// A streamed via 2-stage cp.async. Epilogue stages each 16x128 d block through
// a small smem buffer so global stores are STG.128 (aligned at col==3 mod 4).
#define MSLOTS   37
#define SM_B     0            // 4 chunks x 16384 = 65536
#define SM_A     65536        // 2 stages x 16384 = 32768
#define SM_EN    98304        // 512
#define SM_RED   98816        // sv1 2048 | sv2 2048 | six 2048
#define SM_BUF   104960       // 16 rows x 132 floats = 8448
#define SM_GTOT  113408

__global__ __launch_bounds__(256, 2) void gemm_mma(float* __restrict__ out) {
    extern __shared__ char smem[];
    uint32_t sb = smem_u32(smem);
    int tid  = threadIdx.x;
    int lane = tid & 31, warp = tid >> 5;
    int wy = warp & 1, wx = warp >> 1;          // 2 (M) x 4 (N) warps
    int nidx  = blockIdx.x;
    int mslot = blockIdx.y;
    int j0 = nidx * 128;
    int T  = (mslot < 34) ? 7 : 6;              // 256 = 34*7 + 3*6
    int G  = T * 4;

    float* s_en = (float*)(smem + SM_EN);
    if (tid < 128) s_en[tid] = g_enorm[j0 + tid];

    // ---- Load full B n-tile (4 chunks of 16KB), one cp.async group
    {
#pragma unroll
        for (int kc = 0; kc < 4; kc++)
#pragma unroll
            for (int i = 0; i < 4; i++) {
                int ch = tid + i * 256;           // 0..1023
                int r = ch >> 3, cc = ch & 7;
                uint32_t sw = (uint32_t)(r * 128 + ((cc ^ (r & 7)) << 4));
                cp16(sb + SM_B + kc * 16384 + sw,
                     (const char*)g_Bhi + ((size_t)(j0 + r) * KDIM + kc * 64 + cc * 8) * 2);
            }
        cp_commit();
    }

    // A chunk loader: tile tl, chunk c -> stage s
    auto load_A = [&](int tl, int c, int s) {
        int m0 = (mslot + tl * MSLOTS) * 128;
        uint32_t base = sb + SM_A + s * 16384;
#pragma unroll
        for (int i = 0; i < 4; i++) {
            int ch = tid + i * 256;
            int r = ch >> 3, cc = ch & 7;
            uint32_t sw = (uint32_t)(r * 128 + ((cc ^ (r & 7)) << 4));
            cp16(base + sw,
                 (const char*)g_Ahi + ((size_t)(m0 + r) * KDIM + c * 64 + cc * 8) * 2);
        }
        cp_commit();
    };

    load_A(0, 0, 0);
    load_A(0, 1, 1);

    float acc[4][4][4];
#pragma unroll
    for (int a = 0; a < 4; a++)
#pragma unroll
        for (int b = 0; b < 4; b++)
#pragma unroll
            for (int c = 0; c < 4; c++) acc[a][b][c] = 0.f;

    float* sv1  = (float*)(smem + SM_RED);
    float* sv2  = sv1 + 512;
    int*   six  = (int*)(sv2 + 512);
    float* sbuf = (float*)(smem + SM_BUF);

    for (int g = 0; g < G; g++) {
        int c = g & 3, s = g & 1, tl = g >> 2;
        int m0 = (mslot + tl * MSLOTS) * 128;
        if (g + 2 < G) cp_wait<1>(); else cp_wait<0>();
        __syncthreads();

        uint32_t sa  = sb + SM_A + s * 16384;
        uint32_t sbb = sb + SM_B + c * 16384;
#pragma unroll
        for (int k16 = 0; k16 < 4; k16++) {
            uint32_t af[4][4];
#pragma unroll
            for (int mf = 0; mf < 4; mf++) {
                int row = wy * 64 + mf * 16 + (lane & 15);
                int ch  = k16 * 2 + (lane >> 4);
                uint32_t addr = sa + row * 128 + (((ch ^ (row & 7))) << 4);
                ldsm4(af[mf][0], af[mf][1], af[mf][2], af[mf][3], addr);
            }
            uint32_t bf[4][2];
#pragma unroll
            for (int h = 0; h < 2; h++) {
                int row = wx * 32 + h * 16 + ((lane >> 4) << 3) + (lane & 7);
                int ch  = k16 * 2 + ((lane >> 3) & 1);
                uint32_t addr = sbb + row * 128 + (((ch ^ (row & 7))) << 4);
                uint32_t r0, r1, r2, r3;
                ldsm4(r0, r1, r2, r3, addr);
                bf[2 * h][0] = r0; bf[2 * h][1] = r1;
                bf[2 * h + 1][0] = r2; bf[2 * h + 1][1] = r3;
            }
#pragma unroll
            for (int mf = 0; mf < 4; mf++)
#pragma unroll
                for (int nf = 0; nf < 4; nf++)
                    mma16816(acc[mf][nf], af[mf], bf[nf]);
        }
        __syncthreads();
        if (g + 2 < G) load_A((g + 2) >> 2, (g + 2) & 3, s);

        if (c == 3) {
            // ---- Tile epilogue: per (mf,h) stage 16x128 d values in smem,
            // then store coalesced (STG.128 at col==3 mod 4 + 4 edge scalars).
#pragma unroll
            for (int mf = 0; mf < 4; mf++) {
#pragma unroll
                for (int h = 0; h < 2; h++) {
                    int r4   = lane >> 2;                    // 0..7
                    int row  = wy * 64 + mf * 16 + 8 * h + r4;
                    int brow = wy * 8 + r4;                  // buffer row 0..15
                    float zn = g_znorm[m0 + row];
                    float b1 = 3.4e38f, b2 = 3.4e38f;
                    int   i1 = 0;
                    float* srow = sbuf + brow * 132 + 1 + wx * 32;
#pragma unroll
                    for (int nf = 0; nf < 4; nf++) {
#pragma unroll
                        for (int q = 0; q < 2; q++) {
                            int lcol = nf * 8 + 2 * (lane & 3) + q;
                            int col  = wx * 32 + lcol;
                            float v = fmaf(-2.f, acc[mf][nf][2 * h + q], zn + s_en[col]);
                            srow[lcol] = v;
                            if (v < b1)      { b2 = b1; b1 = v; i1 = j0 + col; }
                            else if (v < b2) { b2 = v; }
                        }
                    }
#pragma unroll
                    for (int off = 1; off < 4; off <<= 1) {
                        float ob1 = __shfl_xor_sync(0xFFFFFFFFu, b1, off);
                        float ob2 = __shfl_xor_sync(0xFFFFFFFFu, b2, off);
                        int   oi1 = __shfl_xor_sync(0xFFFFFFFFu, i1, off);
                        MERGE3(b1, i1, b2, ob1, oi1, ob2);
                    }
                    if ((lane & 3) == 0) {
                        sv1[row * 4 + wx] = b1;
                        sv2[row * 4 + wx] = b2;
                        six[row * 4 + wx] = i1;
                    }
                    __syncthreads();
                    // coalesced writeback of the 16 staged rows
                    {
                        int row16 = tid >> 4;                // 0..15
                        int ii    = tid & 15;                // 0..15
                        int grow  = m0 + ((row16 < 8) ? (mf * 16 + 8 * h + row16)
                                                      : (64 + mf * 16 + 8 * h + row16 - 8));
                        float* drow = out + OFF_D + (size_t)grow * NE + j0;
                        const float* sr = sbuf + row16 * 132 + 1;
                        float4 va = *(const float4*)(sr + 3 + 4 * ii);
                        *(float4*)(drow + 3 + 4 * ii) = va;
                        if (ii < 15) {
                            float4 vb = *(const float4*)(sr + 67 + 4 * ii);
                            *(float4*)(drow + 67 + 4 * ii) = vb;
                        } else {
                            drow[0]   = sr[0];
                            drow[1]   = sr[1];
                            drow[2]   = sr[2];
                            drow[127] = sr[127];
                        }
                    }
                    __syncthreads();
                }
            }
            if (tid < 128) {
                float b1 = sv1[tid * 4], b2 = sv2[tid * 4];
                int   i1 = six[tid * 4];
#pragma unroll
                for (int u = 1; u < 4; u++) {
                    float ob1 = sv1[tid * 4 + u], ob2 = sv2[tid * 4 + u];
                    int   oi1 = six[tid * 4 + u];
                    MERGE3(b1, i1, b2, ob1, oi1, ob2);
                }
                g_pval[nidx][m0 + tid] = b1;
                g_psec[nidx][m0 + tid] = b2;
                g_pidx[nidx][m0 + tid] = i1;
            }
            // reset accumulators for next tile
#pragma unroll
            for (int a = 0; a < 4; a++)
#pragma unroll
                for (int b = 0; b < 4; b++)
#pragma unroll
                    for (int cc2 = 0; cc2 < 4; cc2++) acc[a][b][cc2] = 0.f;
        }
    }
}

// ---------------------------------------------------------------------------
// refine_idx: one warp per token. Merge 8 per-tile triples; for ambiguous
// tokens scan ONLY tiles whose second-best is under threshold (others can
// contribute at most their stored best index). Exact dots read z directly
// from NCHW (identical fp32 values and summation order as before).
__global__ __launch_bounds__(256) void refine_idx(const float* __restrict__ z,
                                                  const float* __restrict__ e,
                                                  float* __restrict__ out) {
    int tid  = threadIdx.x;
    int lane = tid & 31;
    int wid  = tid >> 5;
    int t    = blockIdx.x * 8 + wid;

    float tb1 = 3.4e38f, tb2 = 3.4e38f;
    int   tix = 0x7FFFFFFF;
    if (lane < 8) {
        tb1 = g_pval[lane][t];
        tb2 = g_psec[lane][t];
        tix = g_pidx[lane][t];
    }
    float b1 = tb1, b2 = tb2;
    int   i1 = tix;
#pragma unroll
    for (int off = 1; off < 8; off <<= 1) {
        float ob1 = __shfl_xor_sync(0xFFFFFFFFu, b1, off);
        float ob2 = __shfl_xor_sync(0xFFFFFFFFu, b2, off);
        int   oi1 = __shfl_xor_sync(0xFFFFFFFFu, i1, off);
        MERGE3(b1, i1, b2, ob1, oi1, ob2);
    }
    b1 = __shfl_sync(0xFFFFFFFFu, b1, 0);
    b2 = __shfl_sync(0xFFFFFFFFu, b2, 0);
    i1 = __shfl_sync(0xFFFFFFFFu, i1, 0);

    int besti = i1;
    if (b2 - b1 < REFINE_TH) {
        float thresh = b1 + REFINE_TH;
        int bq  = t >> 10;
        int hw  = t & 1023;
        const float* zb = z + (size_t)bq * KDIM * HW + hw;
        float zr[8];
#pragma unroll
        for (int u = 0; u < 8; u++) zr[u] = zb[(size_t)(lane + 32 * u) * HW];
        float zn    = g_znorm[t];
        float bestv = 3.4e38f;

        // exact-distance evaluator for global code index j (uniform over warp)
        auto eval = [&](int j) {
            const float* erow = e + (size_t)j * KDIM;
            float d = 0.f;
#pragma unroll
            for (int u = 0; u < 8; u++) d = fmaf(zr[u], erow[lane + 32 * u], d);
#pragma unroll
            for (int o = 16; o; o >>= 1) d += __shfl_xor_sync(0xFFFFFFFFu, d, o);
            float ex = fmaf(-2.f, d, zn + g_enorm[j]);
            if (ex < bestv) { bestv = ex; besti = j; }   // ascending j: first-min wins
        };

        // process tiles in ascending order (preserves global ascending-j order)
        for (int u = 0; u < 8; u++) {
            float ub1 = __shfl_sync(0xFFFFFFFFu, tb1, u);
            if (ub1 >= thresh) continue;
            float ub2 = __shfl_sync(0xFFFFFFFFu, tb2, u);
            if (ub2 < thresh) {
                // scan this 128-col tile (candidate set identical to full scan)
                const float* drow = out + OFF_D + (size_t)t * NE + u * 128;
                float dv[4];
#pragma unroll
                for (int k = 0; k < 4; k++) dv[k] = drow[lane + 32 * k];
#pragma unroll
                for (int k = 0; k < 4; k++) {
                    unsigned msk = __ballot_sync(0xFFFFFFFFu, dv[k] < thresh);
                    while (msk) {
                        int src = __ffs(msk) - 1;
                        msk &= msk - 1;
                        eval(u * 128 + src + 32 * k);
                    }
                }
            } else {
                // only the stored best of this tile can be a candidate
                eval(__shfl_sync(0xFFFFFFFFu, tix, u));
            }
        }
    }
    if (lane == 0) {
        g_idx[t] = besti;
        out[OFF_IDX + t] = (float)besti;
    }
}

// ---------------------------------------------------------------------------
// zq_kernel: gather e rows for 32 tokens, write z_q = z + (e - z), loss partials.
__global__ __launch_bounds__(256) void zq_kernel(const float* __restrict__ z,
                                                 const float* __restrict__ e,
                                                 float* __restrict__ out) {
    __shared__ int    s_idx[32];
    __shared__ float  s_e[KDIM][33];
    __shared__ double s_red[8];

    int tid  = threadIdx.x;
    int lane = tid & 31;
    int wid  = tid >> 5;
    int t0   = blockIdx.x * 32;

    if (tid < 32) s_idx[tid] = g_idx[t0 + tid];
    __syncthreads();

#pragma unroll
    for (int u = 0; u < 4; u++) {
        int tt = wid * 4 + u;
        const float* row = e + (size_t)s_idx[tt] * KDIM;
#pragma unroll
        for (int v = 0; v < 8; v++) {
            int c = lane + 32 * v;
            s_e[c][tt] = row[c];
        }
    }
    __syncthreads();

    int b   = t0 >> 10;
    int hw0 = t0 & 1023;
    const float* zb = z + (size_t)b * KDIM * HW + hw0;
    float*       qb = out + OFF_ZQ + (size_t)b * KDIM * HW + hw0;

    float ls = 0.f;
#pragma unroll 4
    for (int ci = 0; ci < 32; ci++) {
        int c = wid + ci * 8;
        float zv  = zb[(size_t)c * HW + lane];
        float ev  = s_e[c][lane];
        float dqz = ev - zv;
        qb[(size_t)c * HW + lane] = zv + dqz;
        ls = fmaf(dqz, dqz, ls);
    }
#pragma unroll
    for (int o = 16; o; o >>= 1) ls += __shfl_xor_sync(0xFFFFFFFFu, ls, o);
    if (lane == 0) s_red[wid] = (double)ls;
    __syncthreads();
    if (tid == 0) {
        double s = 0.0;
#pragma unroll
        for (int u = 0; u < 8; u++) s += s_red[u];
        g_lpart[blockIdx.x] = s;
    }
}

__global__ __launch_bounds__(256) void loss_kernel(float* __restrict__ out) {
    __shared__ double s_red[256];
    int tid = threadIdx.x;
    double s = 0.0;
#pragma unroll
    for (int u = 0; u < 4; u++) s += g_lpart[tid * 4 + u];
    s_red[tid] = s;
    __syncthreads();
    for (int o = 128; o; o >>= 1) {
        if (tid < o) s_red[tid] += s_red[tid + o];
        __syncthreads();
    }
    if (tid == 0) out[OFF_LOSS] = (float)(1.25 * s_red[0] / 8388608.0);
}

// ---------------------------------------------------------------------------
extern "C" void kernel_launch(void* const* d_in, const int* in_sizes, int n_in,
                              void* d_out, int out_size) {
    const float* z = (const float*)d_in[0];
    const float* e = (const float*)d_in[1];
    float* out = (float*)d_out;

    cudaFuncSetAttribute(gemm_mma, cudaFuncAttributeMaxDynamicSharedMemorySize, SM_GTOT);

    prep_e2<<<NE, 128>>>(e);
    prep_z<<<1024, 256>>>(z);
    {
        dim3 grid(8, MSLOTS);       // persistent: n-tile x m-slot
        gemm_mma<<<grid, 256, SM_GTOT>>>(out);
    }
    refine_idx<<<NTOK / 8, 256>>>(z, e, out);
    zq_kernel<<<NTOK / 32, 256>>>(z, e, out);
    loss_kernel<<<1, 256>>>(out);
}

// round 17
// speedup vs baseline: 1.0720x; 1.0088x over previous
#include <cuda_runtime.h>
#include <cuda_bf16.h>
#include <cstdint>

// Problem constants
#define NTOK  32768
#define KDIM  256
#define NE    1024
#define HW    1024

// Output layout (flattened tuple, float32). OFF_D*4 % 16 == 4; but
// (OFF_D + row*1024 + col) is 16B-aligned for col == 3 (mod 4).
#define OFF_ZQ   0
#define OFF_LOSS 8388608
#define OFF_IDX  8388609
#define OFF_D    8421377ll

#define REFINE_TH 2e-3f

// ---------------------------------------------------------------------------
// Scratch (static device arrays; no allocations allowed)
__device__ float  g_znorm[NTOK];
__device__ float  g_enorm[NE];
__device__ float  g_pval[8][NTOK];   // per n-tile best value
__device__ float  g_psec[8][NTOK];   // per n-tile second-best value
__device__ int    g_pidx[8][NTOK];   // per n-tile best index
__device__ int    g_idx[NTOK];       // resolved final index
__device__ double g_lpart[1024];
__device__ unsigned g_done = 0;      // zq completion counter (self-resetting)
__device__ __align__(1024) __nv_bfloat16 g_Ahi[NTOK * KDIM];  // tokens, K-major, bf16
__device__ __align__(1024) __nv_bfloat16 g_Bhi[NE * KDIM];    // codes,  K-major, bf16

// ---------------------------------------------------------------------------
__device__ __forceinline__ uint32_t smem_u32(const void* p) {
    uint32_t a;
    asm("{ .reg .u64 t; cvta.to.shared.u64 t, %1; cvt.u32.u64 %0, t; }" : "=r"(a) : "l"(p));
    return a;
}
__device__ __forceinline__ void cp16(uint32_t dst, const void* src) {
    asm volatile("cp.async.cg.shared.global [%0], [%1], 16;" :: "r"(dst), "l"(src));
}
__device__ __forceinline__ void cp_commit() {
    asm volatile("cp.async.commit_group;" ::: "memory");
}
template <int N> __device__ __forceinline__ void cp_wait() {
    asm volatile("cp.async.wait_group %0;" :: "n"(N) : "memory");
}
__device__ __forceinline__ void ldsm4(uint32_t& r0, uint32_t& r1, uint32_t& r2, uint32_t& r3,
                                      uint32_t addr) {
    asm volatile("ldmatrix.sync.aligned.m8n8.x4.shared.b16 {%0,%1,%2,%3}, [%4];"
                 : "=r"(r0), "=r"(r1), "=r"(r2), "=r"(r3) : "r"(addr));
}
__device__ __forceinline__ void mma16816(float* c, const uint32_t* a, const uint32_t* b) {
    asm volatile(
        "mma.sync.aligned.m16n8k16.row.col.f32.bf16.bf16.f32 "
        "{%0,%1,%2,%3}, {%4,%5,%6,%7}, {%8,%9}, {%0,%1,%2,%3};"
        : "+f"(c[0]), "+f"(c[1]), "+f"(c[2]), "+f"(c[3])
        : "r"(a[0]), "r"(a[1]), "r"(a[2]), "r"(a[3]), "r"(b[0]), "r"(b[1]));
}
// Merge (b1,i1,b2) <- other (ob1,oi1,ob2); strict compare + index tie-break.
#define MERGE3(b1, i1, b2, ob1, oi1, ob2) do {                     \
    if ((ob1) < (b1) || ((ob1) == (b1) && (oi1) < (i1))) {         \
        (b2) = fminf((b1), (ob2)); (b1) = (ob1); (i1) = (oi1);     \
    } else {                                                       \
        (b2) = fminf((b2), (ob1));                                 \
    }                                                              \
} while (0)

// ---------------------------------------------------------------------------
// prep_z: NCHW -> token-major bf16 (g_Ahi) + znorm; ALSO converts e row
// blockIdx.x to bf16 + enorm (fused prep_e). 32 tokens/block, 1024 blocks.
__global__ __launch_bounds__(256) void prep_z(const float* __restrict__ z,
                                              const float* __restrict__ e) {
    __shared__ float ts[KDIM][33];
    __shared__ float zp[8][32];
    __shared__ float ewsum[4];
    int tid = threadIdx.x;
    int tb  = blockIdx.x;
    int lane32 = tid & 31;

    // ---- fused prep_e: e row tb (first 128 threads)
    if (tid < 128) {
        float2 v = ((const float2*)e)[tb * 128 + tid];
        __nv_bfloat162 hp;
        hp.x = __float2bfloat16(v.x);
        hp.y = __float2bfloat16(v.y);
        ((uint32_t*)g_Bhi)[tb * 128 + tid] = *(uint32_t*)&hp;
        float s = fmaf(v.x, v.x, v.y * v.y);
#pragma unroll
        for (int o = 16; o; o >>= 1) s += __shfl_xor_sync(0xFFFFFFFFu, s, o);
        if (lane32 == 0) ewsum[tid >> 5] = s;
    }

    // ---- z tile load
    int b   = tb >> 5;
    int hw0 = (tb * 32) & 1023;
    const float* zb = z + (size_t)b * KDIM * HW + hw0;
    int cb = tid >> 5;
#pragma unroll
    for (int i = 0; i < 32; i++) {
        int c = i * 8 + cb;
        ts[c][lane32] = zb[(size_t)c * HW + lane32];
    }
    __syncthreads();
    if (tid == 0) g_enorm[tb] = ewsum[0] + ewsum[1] + ewsum[2] + ewsum[3];
    // znorm partials
    float s = 0.f;
#pragma unroll
    for (int i = 0; i < 32; i++) {
        float v = ts[cb * 32 + i][lane32];
        s = fmaf(v, v, s);
    }
    zp[cb][lane32] = s;
    __syncthreads();
    if (tid < 32) {
        float t = 0.f;
#pragma unroll
        for (int u = 0; u < 8; u++) t += zp[u][tid];
        g_znorm[tb * 32 + tid] = t;
    }
    // write bf16 token rows
    int t = tid >> 3, part = tid & 7;
    uint32_t* ah = (uint32_t*)g_Ahi + (size_t)(tb * 32 + t) * 128 + part * 16;
#pragma unroll
    for (int i = 0; i < 16; i++) {
        __nv_bfloat162 hp;
        hp.x = __float2bfloat16(ts[part * 32 + 2 * i][t]);
        hp.y = __float2bfloat16(ts[part * 32 + 2 * i + 1][t]);
        ah[i] = *(uint32_t*)&hp;
    }
}

// ---------------------------------------------------------------------------
// Persistent GEMM: grid (8 n-tiles, 37 m-slots). B n-tile resident in SMEM;
// A streamed via 2-stage cp.async. Epilogue stages each 16x128 d block through
// a small smem buffer so global stores are STG.128 (aligned at col==3 mod 4).
#define MSLOTS   37
#define SM_B     0            // 4 chunks x 16384 = 65536
#define SM_A     65536        // 2 stages x 16384 = 32768
#define SM_EN    98304        // 512
#define SM_RED   98816        // sv1 2048 | sv2 2048 | six 2048
#define SM_BUF   104960       // 16 rows x 132 floats = 8448
#define SM_GTOT  113408

__global__ __launch_bounds__(256, 2) void gemm_mma(float* __restrict__ out) {
    extern __shared__ char smem[];
    uint32_t sb = smem_u32(smem);
    int tid  = threadIdx.x;
    int lane = tid & 31, warp = tid >> 5;
    int wy = warp & 1, wx = warp >> 1;          // 2 (M) x 4 (N) warps
    int nidx  = blockIdx.x;
    int mslot = blockIdx.y;
    int j0 = nidx * 128;
    int T  = (mslot < 34) ? 7 : 6;              // 256 = 34*7 + 3*6
    int G  = T * 4;

    float* s_en = (float*)(smem + SM_EN);
    if (tid < 128) s_en[tid] = g_enorm[j0 + tid];

    // ---- Load full B n-tile (4 chunks of 16KB), one cp.async group
    {
#pragma unroll
        for (int kc = 0; kc < 4; kc++)
#pragma unroll
            for (int i = 0; i < 4; i++) {
                int ch = tid + i * 256;           // 0..1023
                int r = ch >> 3, cc = ch & 7;
                uint32_t sw = (uint32_t)(r * 128 + ((cc ^ (r & 7)) << 4));
                cp16(sb + SM_B + kc * 16384 + sw,
                     (const char*)g_Bhi + ((size_t)(j0 + r) * KDIM + kc * 64 + cc * 8) * 2);
            }
        cp_commit();
    }

    // A chunk loader: tile tl, chunk c -> stage s
    auto load_A = [&](int tl, int c, int s) {
        int m0 = (mslot + tl * MSLOTS) * 128;
        uint32_t base = sb + SM_A + s * 16384;
#pragma unroll
        for (int i = 0; i < 4; i++) {
            int ch = tid + i * 256;
            int r = ch >> 3, cc = ch & 7;
            uint32_t sw = (uint32_t)(r * 128 + ((cc ^ (r & 7)) << 4));
            cp16(base + sw,
                 (const char*)g_Ahi + ((size_t)(m0 + r) * KDIM + c * 64 + cc * 8) * 2);
        }
        cp_commit();
    };

    load_A(0, 0, 0);
    load_A(0, 1, 1);

    float acc[4][4][4];
#pragma unroll
    for (int a = 0; a < 4; a++)
#pragma unroll
        for (int b = 0; b < 4; b++)
#pragma unroll
            for (int c = 0; c < 4; c++) acc[a][b][c] = 0.f;

    float* sv1  = (float*)(smem + SM_RED);
    float* sv2  = sv1 + 512;
    int*   six  = (int*)(sv2 + 512);
    float* sbuf = (float*)(smem + SM_BUF);

    for (int g = 0; g < G; g++) {
        int c = g & 3, s = g & 1, tl = g >> 2;
        int m0 = (mslot + tl * MSLOTS) * 128;
        if (g + 2 < G) cp_wait<1>(); else cp_wait<0>();
        __syncthreads();

        uint32_t sa  = sb + SM_A + s * 16384;
        uint32_t sbb = sb + SM_B + c * 16384;
#pragma unroll
        for (int k16 = 0; k16 < 4; k16++) {
            uint32_t af[4][4];
#pragma unroll
            for (int mf = 0; mf < 4; mf++) {
                int row = wy * 64 + mf * 16 + (lane & 15);
                int ch  = k16 * 2 + (lane >> 4);
                uint32_t addr = sa + row * 128 + (((ch ^ (row & 7))) << 4);
                ldsm4(af[mf][0], af[mf][1], af[mf][2], af[mf][3], addr);
            }
            uint32_t bf[4][2];
#pragma unroll
            for (int h = 0; h < 2; h++) {
                int row = wx * 32 + h * 16 + ((lane >> 4) << 3) + (lane & 7);
                int ch  = k16 * 2 + ((lane >> 3) & 1);
                uint32_t addr = sbb + row * 128 + (((ch ^ (row & 7))) << 4);
                uint32_t r0, r1, r2, r3;
                ldsm4(r0, r1, r2, r3, addr);
                bf[2 * h][0] = r0; bf[2 * h][1] = r1;
                bf[2 * h + 1][0] = r2; bf[2 * h + 1][1] = r3;
            }
#pragma unroll
            for (int mf = 0; mf < 4; mf++)
#pragma unroll
                for (int nf = 0; nf < 4; nf++)
                    mma16816(acc[mf][nf], af[mf], bf[nf]);
        }
        __syncthreads();
        if (g + 2 < G) load_A((g + 2) >> 2, (g + 2) & 3, s);

        if (c == 3) {
            // ---- Tile epilogue: per (mf,h) stage 16x128 d values in smem,
            // then store coalesced (STG.128 at col==3 mod 4 + 4 edge scalars).
#pragma unroll
            for (int mf = 0; mf < 4; mf++) {
#pragma unroll
                for (int h = 0; h < 2; h++) {
                    int r4   = lane >> 2;                    // 0..7
                    int row  = wy * 64 + mf * 16 + 8 * h + r4;
                    int brow = wy * 8 + r4;                  // buffer row 0..15
                    float zn = g_znorm[m0 + row];
                    float b1 = 3.4e38f, b2 = 3.4e38f;
                    int   i1 = 0;
                    float* srow = sbuf + brow * 132 + 1 + wx * 32;
#pragma unroll
                    for (int nf = 0; nf < 4; nf++) {
#pragma unroll
                        for (int q = 0; q < 2; q++) {
                            int lcol = nf * 8 + 2 * (lane & 3) + q;
                            int col  = wx * 32 + lcol;
                            float v = fmaf(-2.f, acc[mf][nf][2 * h + q], zn + s_en[col]);
                            srow[lcol] = v;
                            if (v < b1)      { b2 = b1; b1 = v; i1 = j0 + col; }
                            else if (v < b2) { b2 = v; }
                        }
                    }
#pragma unroll
                    for (int off = 1; off < 4; off <<= 1) {
                        float ob1 = __shfl_xor_sync(0xFFFFFFFFu, b1, off);
                        float ob2 = __shfl_xor_sync(0xFFFFFFFFu, b2, off);
                        int   oi1 = __shfl_xor_sync(0xFFFFFFFFu, i1, off);
                        MERGE3(b1, i1, b2, ob1, oi1, ob2);
                    }
                    if ((lane & 3) == 0) {
                        sv1[row * 4 + wx] = b1;
                        sv2[row * 4 + wx] = b2;
                        six[row * 4 + wx] = i1;
                    }
                    __syncthreads();
                    // coalesced writeback of the 16 staged rows
                    {
                        int row16 = tid >> 4;                // 0..15
                        int ii    = tid & 15;                // 0..15
                        int grow  = m0 + ((row16 < 8) ? (mf * 16 + 8 * h + row16)
                                                      : (64 + mf * 16 + 8 * h + row16 - 8));
                        float* drow = out + OFF_D + (size_t)grow * NE + j0;
                        const float* sr = sbuf + row16 * 132 + 1;
                        float4 va = *(const float4*)(sr + 3 + 4 * ii);
                        *(float4*)(drow + 3 + 4 * ii) = va;
                        if (ii < 15) {
                            float4 vb = *(const float4*)(sr + 67 + 4 * ii);
                            *(float4*)(drow + 67 + 4 * ii) = vb;
                        } else {
                            drow[0]   = sr[0];
                            drow[1]   = sr[1];
                            drow[2]   = sr[2];
                            drow[127] = sr[127];
                        }
                    }
                    __syncthreads();
                }
            }
            if (tid < 128) {
                float b1 = sv1[tid * 4], b2 = sv2[tid * 4];
                int   i1 = six[tid * 4];
#pragma unroll
                for (int u = 1; u < 4; u++) {
                    float ob1 = sv1[tid * 4 + u], ob2 = sv2[tid * 4 + u];
                    int   oi1 = six[tid * 4 + u];
                    MERGE3(b1, i1, b2, ob1, oi1, ob2);
                }
                g_pval[nidx][m0 + tid] = b1;
                g_psec[nidx][m0 + tid] = b2;
                g_pidx[nidx][m0 + tid] = i1;
            }
            // reset accumulators for next tile
#pragma unroll
            for (int a = 0; a < 4; a++)
#pragma unroll
                for (int b = 0; b < 4; b++)
#pragma unroll
                    for (int cc2 = 0; cc2 < 4; cc2++) acc[a][b][cc2] = 0.f;
        }
    }
}

// ---------------------------------------------------------------------------
// refine_idx: one warp per token. Merge 8 per-tile triples; for ambiguous
// tokens scan ONLY tiles whose second-best is under threshold (others can
// contribute at most their stored best index). Exact dots read z directly
// from NCHW.
__global__ __launch_bounds__(256) void refine_idx(const float* __restrict__ z,
                                                  const float* __restrict__ e,
                                                  float* __restrict__ out) {
    int tid  = threadIdx.x;
    int lane = tid & 31;
    int wid  = tid >> 5;
    int t    = blockIdx.x * 8 + wid;

    float tb1 = 3.4e38f, tb2 = 3.4e38f;
    int   tix = 0x7FFFFFFF;
    if (lane < 8) {
        tb1 = g_pval[lane][t];
        tb2 = g_psec[lane][t];
        tix = g_pidx[lane][t];
    }
    float b1 = tb1, b2 = tb2;
    int   i1 = tix;
#pragma unroll
    for (int off = 1; off < 8; off <<= 1) {
        float ob1 = __shfl_xor_sync(0xFFFFFFFFu, b1, off);
        float ob2 = __shfl_xor_sync(0xFFFFFFFFu, b2, off);
        int   oi1 = __shfl_xor_sync(0xFFFFFFFFu, i1, off);
        MERGE3(b1, i1, b2, ob1, oi1, ob2);
    }
    b1 = __shfl_sync(0xFFFFFFFFu, b1, 0);
    b2 = __shfl_sync(0xFFFFFFFFu, b2, 0);
    i1 = __shfl_sync(0xFFFFFFFFu, i1, 0);

    int besti = i1;
    if (b2 - b1 < REFINE_TH) {
        float thresh = b1 + REFINE_TH;
        int bq  = t >> 10;
        int hw  = t & 1023;
        const float* zb = z + (size_t)bq * KDIM * HW + hw;
        float zr[8];
#pragma unroll
        for (int u = 0; u < 8; u++) zr[u] = zb[(size_t)(lane + 32 * u) * HW];
        float zn    = g_znorm[t];
        float bestv = 3.4e38f;

        // exact-distance evaluator for global code index j (uniform over warp)
        auto eval = [&](int j) {
            const float* erow = e + (size_t)j * KDIM;
            float d = 0.f;
#pragma unroll
            for (int u = 0; u < 8; u++) d = fmaf(zr[u], erow[lane + 32 * u], d);
#pragma unroll
            for (int o = 16; o; o >>= 1) d += __shfl_xor_sync(0xFFFFFFFFu, d, o);
            float ex = fmaf(-2.f, d, zn + g_enorm[j]);
            if (ex < bestv) { bestv = ex; besti = j; }   // ascending j: first-min wins
        };

        // process tiles in ascending order (preserves global ascending-j order)
        for (int u = 0; u < 8; u++) {
            float ub1 = __shfl_sync(0xFFFFFFFFu, tb1, u);
            if (ub1 >= thresh) continue;
            float ub2 = __shfl_sync(0xFFFFFFFFu, tb2, u);
            if (ub2 < thresh) {
                // scan this 128-col tile (candidate set identical to full scan)
                const float* drow = out + OFF_D + (size_t)t * NE + u * 128;
                float dv[4];
#pragma unroll
                for (int k = 0; k < 4; k++) dv[k] = drow[lane + 32 * k];
#pragma unroll
                for (int k = 0; k < 4; k++) {
                    unsigned msk = __ballot_sync(0xFFFFFFFFu, dv[k] < thresh);
                    while (msk) {
                        int src = __ffs(msk) - 1;
                        msk &= msk - 1;
                        eval(u * 128 + src + 32 * k);
                    }
                }
            } else {
                // only the stored best of this tile can be a candidate
                eval(__shfl_sync(0xFFFFFFFFu, tix, u));
            }
        }
    }
    if (lane == 0) {
        g_idx[t] = besti;
        out[OFF_IDX + t] = (float)besti;
    }
}

// ---------------------------------------------------------------------------
// zq_kernel: gather e rows for 32 tokens, write z_q = z + (e - z), loss
// partials; the LAST finishing block performs the deterministic final loss
// reduction (fixed-order sum over g_lpart) and resets the counter.
__global__ __launch_bounds__(256) void zq_kernel(const float* __restrict__ z,
                                                 const float* __restrict__ e,
                                                 float* __restrict__ out) {
    __shared__ int    s_idx[32];
    __shared__ float  s_e[KDIM][33];
    __shared__ double s_red[8];
    __shared__ double s_fin[256];
    __shared__ int    s_last;

    int tid  = threadIdx.x;
    int lane = tid & 31;
    int wid  = tid >> 5;
    int t0   = blockIdx.x * 32;

    if (tid < 32) s_idx[tid] = g_idx[t0 + tid];
    __syncthreads();

#pragma unroll
    for (int u = 0; u < 4; u++) {
        int tt = wid * 4 + u;
        const float* row = e + (size_t)s_idx[tt] * KDIM;
#pragma unroll
        for (int v = 0; v < 8; v++) {
            int c = lane + 32 * v;
            s_e[c][tt] = row[c];
        }
    }
    __syncthreads();

    int b   = t0 >> 10;
    int hw0 = t0 & 1023;
    const float* zb = z + (size_t)b * KDIM * HW + hw0;
    float*       qb = out + OFF_ZQ + (size_t)b * KDIM * HW + hw0;

    float ls = 0.f;
#pragma unroll 4
    for (int ci = 0; ci < 32; ci++) {
        int c = wid + ci * 8;
        float zv  = zb[(size_t)c * HW + lane];
        float ev  = s_e[c][lane];
        float dqz = ev - zv;
        qb[(size_t)c * HW + lane] = zv + dqz;
        ls = fmaf(dqz, dqz, ls);
    }
#pragma unroll
    for (int o = 16; o; o >>= 1) ls += __shfl_xor_sync(0xFFFFFFFFu, ls, o);
    if (lane == 0) s_red[wid] = (double)ls;
    __syncthreads();
    if (tid == 0) {
        double s = 0.0;
#pragma unroll
        for (int u = 0; u < 8; u++) s += s_red[u];
        g_lpart[blockIdx.x] = s;
        __threadfence();
        unsigned r = atomicAdd(&g_done, 1u);
        s_last = (r == 1023u);
    }
    __syncthreads();

    if (s_last) {
        // deterministic final reduction (fixed order, independent of which
        // block executes it)
        double s = 0.0;
#pragma unroll
        for (int u = 0; u < 4; u++) s += g_lpart[tid * 4 + u];
        s_fin[tid] = s;
        __syncthreads();
        for (int o = 128; o; o >>= 1) {
            if (tid < o) s_fin[tid] += s_fin[tid + o];
            __syncthreads();
        }
        if (tid == 0) {
            out[OFF_LOSS] = (float)(1.25 * s_fin[0] / 8388608.0);
            g_done = 0;                 // self-reset for next graph replay
        }
    }
}

// ---------------------------------------------------------------------------
extern "C" void kernel_launch(void* const* d_in, const int* in_sizes, int n_in,
                              void* d_out, int out_size) {
    const float* z = (const float*)d_in[0];
    const float* e = (const float*)d_in[1];
    float* out = (float*)d_out;

    cudaFuncSetAttribute(gemm_mma, cudaFuncAttributeMaxDynamicSharedMemorySize, SM_GTOT);

    prep_z<<<1024, 256>>>(z, e);
    {
        dim3 grid(8, MSLOTS);       // persistent: n-tile x m-slot
        gemm_mma<<<grid, 256, SM_GTOT>>>(out);
    }
    refine_idx<<<NTOK / 8, 256>>>(z, e, out);
    zq_kernel<<<NTOK / 32, 256>>>(z, e, out);
}